// round 8
// baseline (speedup 1.0000x reference)
#include <cuda_runtime.h>

// PZCell biquad: warp-per-row, single parallel scan over the whole row.
// y[t] = b0 x[t] + b1 x[t-1] + b2 x[t-2] - a1 y[t-1] - a2 y[t-2]   (den == 1)
// 32 lanes x 64 steps in one swizzled 8KB SMEM tile per warp:
//   cp.async load (4 groups) -> Phase A zero-state recurrence in place ->
//   one affine Kogge-Stone scan (T = M^64) -> transposed store pass with
//   fused homogeneous correction (W = M^(4*(lane&15))).

namespace {
constexpr int T_LEN   = 2048;
constexpr int B_ROWS  = 4096;
constexpr int L       = 64;                 // steps per lane
constexpr int RPB     = 2;                  // rows (warps) per block
constexpr int THREADS = 32 * RPB;
constexpr int TILE    = 2048;               // floats per warp tile (8KB)
constexpr int SMEM_BYTES = RPB * TILE * (int)sizeof(float);  // 16384
}

// chunk c (0..31, 64 floats), granule g (0..15): XOR swizzle, conflict-free
// per quarter-warp for all three access patterns.
__device__ __forceinline__ int swz(int c, int g) {
    return c * 64 + ((g ^ (c & 15)) << 2);
}

__device__ __forceinline__ void cp_async16(float* dst, const float* src) {
    unsigned s = (unsigned)__cvta_generic_to_shared(dst);
    asm volatile("cp.async.cg.shared.global [%0], [%1], 16;" :: "r"(s), "l"(src));
}
__device__ __forceinline__ void cp_commit() { asm volatile("cp.async.commit_group;"); }
__device__ __forceinline__ void cp_wait0()  { asm volatile("cp.async.wait_group 0;" ::: "memory"); }

struct Coef { float a1, a2, A2, Bc, b0, b1, b2; };
struct Mat  { float m00, m01, m10, m11; };

__device__ __forceinline__ Mat mat_sq(const Mat& a) {
    Mat r;
    r.m00 = a.m00*a.m00 + a.m01*a.m10;  r.m01 = a.m00*a.m01 + a.m01*a.m11;
    r.m10 = a.m10*a.m00 + a.m11*a.m10;  r.m11 = a.m10*a.m01 + a.m11*a.m11;
    return r;
}
__device__ __forceinline__ Mat mat_mul(const Mat& a, const Mat& b) {
    Mat r;
    r.m00 = a.m00*b.m00 + a.m01*b.m10;  r.m01 = a.m00*b.m01 + a.m01*b.m11;
    r.m10 = a.m10*b.m00 + a.m11*b.m10;  r.m11 = a.m10*b.m01 + a.m11*b.m11;
    return r;
}

__global__ void __launch_bounds__(THREADS, 14)
pz8_kernel(const float* __restrict__ x, const float* __restrict__ gain_ri,
           const float* __restrict__ poles_ri, const float* __restrict__ zeros_ri,
           float* __restrict__ out)
{
    extern __shared__ float sbuf[];
    const int lane = threadIdx.x & 31;
    const int w    = threadIdx.x >> 5;
    const int row  = blockIdx.x * RPB + w;
    const float* xr = x   + (long)row * T_LEN;
    float*       yr = out + (long)row * T_LEN;
    float* tile = sbuf + w * TILE;

    // ---- cp.async load of the whole row, 4 commit groups ----
    #pragma unroll
    for (int k = 0; k < 16; ++k) {
        int ch = 2 * k + (lane >> 4);
        cp_async16(tile + swz(ch, lane & 15), xr + k * 128 + lane * 4);
        if ((k & 3) == 3) cp_commit();
    }

    // ---- coefficients + matrix powers (overlap with loads) ----
    Coef c;
    {
        const float gr = gain_ri[0],  gi = gain_ri[1];
        const float pr0 = poles_ri[0], pi0 = poles_ri[1];
        const float pr1 = poles_ri[2], pi1 = poles_ri[3];
        const float zr0 = zeros_ri[0], zi0 = zeros_ri[1];
        const float zr1 = zeros_ri[2], zi1 = zeros_ri[3];
        c.a1 = -(pr0 + pr1);
        c.a2 = pr0 * pr1 - pi0 * pi1;
        const float zc1r = -(zr0 + zr1), zc1i = -(zi0 + zi1);
        const float zc2r = zr0 * zr1 - zi0 * zi1;
        const float zc2i = zr0 * zi1 + zi0 * zr1;
        c.b0 = gr;
        c.b1 = gr * zc1r - gi * zc1i;
        c.b2 = gr * zc2r - gi * zc2i;
        c.A2 = c.a1 * c.a1 - c.a2;
        c.Bc = c.a1 * c.a2;
    }
    Mat M1  = { -c.a1, -c.a2, 1.f, 0.f };
    Mat M4  = mat_sq(mat_sq(M1));
    Mat M8  = mat_sq(M4);
    Mat M16 = mat_sq(M8);
    Mat M32 = mat_sq(M16);
    Mat M64 = mat_sq(M32);
    Mat W   = { 1.f, 0.f, 0.f, 1.f };        // W = M^(4*(lane&15))
    if (lane & 1) W = M4;
    if (lane & 2) W = mat_mul(M8,  W);
    if (lane & 4) W = mat_mul(M16, W);
    if (lane & 8) W = mat_mul(M32, W);

    cp_wait0();
    __syncwarp();

    // ---- boundary x[-1], x[-2]: tail of previous lane's chunk ----
    float x1 = 0.f, x2 = 0.f;
    if (lane > 0) {
        int cc = lane - 1;
        int off = cc * 64 + ((15 ^ (cc & 15)) << 2);   // granule 15 = steps 60..63
        x1 = tile[off + 3];   // step 63
        x2 = tile[off + 2];   // step 62
    }
    __syncwarp();

    // ---- Phase A: zero-entry-state recurrence in place ----
    float p = 0.f, q = 0.f;
    #pragma unroll
    for (int g = 0; g < 16; ++g) {
        float4 xv = *reinterpret_cast<float4*>(tile + swz(lane, g));
        float u0 = fmaf(c.b0, xv.x, fmaf(c.b1, x1,   c.b2 * x2));
        float u1 = fmaf(c.b0, xv.y, fmaf(c.b1, xv.x, c.b2 * x1));
        float u2 = fmaf(c.b0, xv.z, fmaf(c.b1, xv.y, c.b2 * xv.x));
        float u3 = fmaf(c.b0, xv.w, fmaf(c.b1, xv.z, c.b2 * xv.y));
        x2 = xv.z; x1 = xv.w;
        float w1 = fmaf(-c.a1, u0, u1);
        float w3 = fmaf(-c.a1, u2, u3);
        float yA = fmaf(-c.a1, p,  fmaf(-c.a2, q,  u0));
        float yB = fmaf( c.A2, p,  fmaf( c.Bc, q,  w1));
        float yC = fmaf(-c.a1, yB, fmaf(-c.a2, yA, u2));
        float yD = fmaf( c.A2, yB, fmaf( c.Bc, yA, w3));
        p = yD; q = yC;
        *reinterpret_cast<float4*>(tile + swz(lane, g)) = make_float4(yA, yB, yC, yD);
    }

    // ---- affine Kogge-Stone scan over lanes (T = M^64) ----
    Mat m = M64;
    float vx = p, vy = q;
    #pragma unroll
    for (int i = 0; i < 5; ++i) {
        float ox = __shfl_up_sync(0xffffffffu, vx, 1u << i);
        float oy = __shfl_up_sync(0xffffffffu, vy, 1u << i);
        if (lane >= (1 << i)) {
            vx = fmaf(m.m00, ox, fmaf(m.m01, oy, vx));
            vy = fmaf(m.m10, ox, fmaf(m.m11, oy, vy));
        }
        if (i < 4) m = mat_sq(m);
    }
    // exclusive entry state per chunk (lane 0 entry = 0: true row start)
    float ex = __shfl_up_sync(0xffffffffu, vx, 1);
    float ey = __shfl_up_sync(0xffffffffu, vy, 1);
    if (lane == 0) { ex = 0.f; ey = 0.f; }

    __syncwarp();

    // ---- transposed store pass with fused homogeneous correction ----
    // lane handles float4 at p = k*128 + lane*4: chunk ch = 2k + (lane>>4),
    // intra-chunk offset f0 = (lane&15)*4, seed = W * entry(ch).
    #pragma unroll
    for (int k = 0; k < 16; ++k) {
        int ch = 2 * k + (lane >> 4);
        float exc = __shfl_sync(0xffffffffu, ex, ch);
        float eyc = __shfl_sync(0xffffffffu, ey, ch);
        float s1 = fmaf(W.m00, exc, W.m01 * eyc);
        float s2 = fmaf(W.m10, exc, W.m11 * eyc);
        float hA = fmaf(-c.a1, s1, -c.a2 * s2);
        float hB = fmaf( c.A2, s1,  c.Bc * s2);
        float hC = fmaf(-c.a1, hB, -c.a2 * hA);
        float hD = fmaf( c.A2, hB,  c.Bc * hA);
        float4 zv = *reinterpret_cast<float4*>(tile + swz(ch, lane & 15));
        zv.x += hA; zv.y += hB; zv.z += hC; zv.w += hD;
        *reinterpret_cast<float4*>(yr + k * 128 + lane * 4) = zv;
    }
}

extern "C" void kernel_launch(void* const* d_in, const int* in_sizes, int n_in,
                              void* d_out, int out_size) {
    (void)in_sizes; (void)n_in; (void)out_size;
    const float* x        = (const float*)d_in[0];
    const float* gain_ri  = (const float*)d_in[1];
    const float* poles_ri = (const float*)d_in[2];
    const float* zeros_ri = (const float*)d_in[3];
    float* out = (float*)d_out;

    cudaFuncSetAttribute(pz8_kernel, cudaFuncAttributeMaxDynamicSharedMemorySize, SMEM_BYTES);
    pz8_kernel<<<B_ROWS / RPB, THREADS, SMEM_BYTES>>>(x, gain_ri, poles_ri, zeros_ri, out);
}